// round 17
// baseline (speedup 1.0000x reference)
#include <cuda_runtime.h>
#include <cuda_bf16.h>

#define B 2
#define H 8
#define T 384
#define S 384
#define D 64
#define BH (B*H)            // 16
#define TTB 16              // t-rows per block
#define SC 64               // s-chunk width (split across warp halves)
#define NBLK (BH * (T/TTB)) // 384

// Scratch for projected q/k (allocation-free: device globals)
__device__ float g_qp[BH * T * D];   // (bh, t, e)
__device__ float g_kp[BH * S * D];   // (bh, s, e)

__device__ __forceinline__ float tanh_fast(float x) {
    float y;
    asm("tanh.approx.f32 %0, %1;" : "=f"(y) : "f"(x));
    return y;
}

// ---------------------------------------------------------------------------
// Kernel 1: qp = q @ Wq^T, kp = k @ Wk^T   (rows = BH*T = 6144 each)
// ---------------------------------------------------------------------------
__global__ __launch_bounds__(256) void proj_kernel(
    const float* __restrict__ q, const float* __restrict__ k,
    const float* __restrict__ Wq, const float* __restrict__ Wk)
{
    __shared__ __align__(16) float sW[2][64][68];   // [q/k][e][d], padded
    __shared__ __align__(16) float sx[4][64];

    for (int i = threadIdx.x; i < 64 * 64; i += 256) {
        int e = i >> 6, d = i & 63;
        sW[0][e][d] = Wq[i];
        sW[1][e][d] = Wk[i];
    }

    const int NR = BH * T;                // 6144
    const int which  = threadIdx.x >> 6;  // 0..3
    const int lane64 = threadIdx.x & 63;  // e index
    const int m = which & 1;              // 0=q, 1=k

    for (int r0 = blockIdx.x * 2; r0 < NR; r0 += gridDim.x * 2) {
        __syncthreads();
        const float* src = m ? k : q;
        int r = r0 + (which >> 1);
        sx[which][lane64] = src[r * 64 + lane64];
        __syncthreads();

        float acc = 0.0f;
        #pragma unroll
        for (int j = 0; j < 16; ++j) {
            float4 w = *(const float4*)&sW[m][lane64][4 * j];
            float4 x = *(const float4*)&sx[which][4 * j];
            acc = fmaf(w.x, x.x, acc);
            acc = fmaf(w.y, x.y, acc);
            acc = fmaf(w.z, x.z, acc);
            acc = fmaf(w.w, x.w, acc);
        }
        float* dst = m ? g_kp : g_qp;
        dst[r * 64 + lane64] = acc;
    }
}

// ---------------------------------------------------------------------------
// Kernel 2: 512 threads = 16 warps. Warp w (w<8) owns t-rows {w, w+8} for the
// low 32 s of each 64-wide chunk; warp w+8 owns the same rows for the high 32.
// Occupancy: grid 384 x 16 warps ~= 42 warps/SM resident.
// ---------------------------------------------------------------------------
__global__ __launch_bounds__(512, 2) void attn_kernel(
    const float* __restrict__ value,
    const float* __restrict__ v_w,
    float* __restrict__ out,        // (bh, t, d)
    float* __restrict__ attn_out)   // (bh, t, s)
{
    __shared__ __align__(16) float sh_score[TTB][S];  // 24576 B
    __shared__ __align__(16) float sh_u[5504];        // 22016 B (union)

    // Phase-1 view: uqp[16][68] | ukp[64][68] | uvw[64]
    float (*uqp)[68] = (float(*)[68])sh_u;              // 1088 floats
    float (*ukp)[68] = (float(*)[68])(sh_u + 1088);     // 4352 floats
    float* uvw       = sh_u + 1088 + 4352;              // 64 floats
    // Phase-2 view (AV partials): sh_u as [4][16][64] (first 4096 floats)

    const int tile = blockIdx.x;
    const int bh = tile / (T / TTB);
    const int t0 = (tile % (T / TTB)) * TTB;

    const int tid  = threadIdx.x;
    const int warp = tid >> 5;        // 0..15
    const int lane = tid & 31;
    const int wr   = warp & 7;        // row pair: rows wr, wr+8
    const int sh   = (warp >> 3) * 32; // s offset within chunk: 0 or 32

    // Stage qp tile (16 rows x 16 float4) + v_w
    if (tid < 256) {
        int tt = tid >> 4, j = tid & 15;
        *((float4*)&uqp[tt][0] + j) =
            *((const float4*)&g_qp[(bh * T + t0 + tt) * D] + j);
    }
    if (tid < D) uvw[tid] = v_w[tid];
    __syncthreads();

    // ---- Score phase: 6 chunks of 64 s-values ----
    for (int sc = 0; sc < S / SC; ++sc) {
        #pragma unroll
        for (int kk = 0; kk < 2; ++kk) {
            int i4 = tid + kk * 512;           // 1024 float4 total (64 rows)
            int ss = i4 >> 4, j = i4 & 15;
            *((float4*)&ukp[ss][0] + j) =
                *((const float4*)&g_kp[(bh * S + sc * SC + ss) * D] + j);
        }
        __syncthreads();

        const int sl = sh + lane;  // s within chunk, 0..63
        float a0 = 0.0f, a1 = 0.0f;
        #pragma unroll
        for (int j = 0; j < 16; ++j) {
            float4 kq = *((const float4*)&ukp[sl][0] + j);
            float4 wv = *((const float4*)&uvw[4 * j]);
            float4 q0 = *((const float4*)&uqp[wr][0] + j);
            float4 q1 = *((const float4*)&uqp[wr + 8][0] + j);
            a0 = fmaf(wv.x, tanh_fast(q0.x + kq.x), a0);
            a1 = fmaf(wv.x, tanh_fast(q1.x + kq.x), a1);
            a0 = fmaf(wv.y, tanh_fast(q0.y + kq.y), a0);
            a1 = fmaf(wv.y, tanh_fast(q1.y + kq.y), a1);
            a0 = fmaf(wv.z, tanh_fast(q0.z + kq.z), a0);
            a1 = fmaf(wv.z, tanh_fast(q1.z + kq.z), a1);
            a0 = fmaf(wv.w, tanh_fast(q0.w + kq.w), a0);
            a1 = fmaf(wv.w, tanh_fast(q1.w + kq.w), a1);
        }
        sh_score[wr][sc * SC + sl]     = a0;
        sh_score[wr + 8][sc * SC + sl] = a1;
        __syncthreads();
    }

    // ---- Softmax: one row per warp (16 rows, 16 warps) ----
    {
        const int rr = warp;
        const int NPL = S / 32;  // 12
        float vals[NPL];
        float m = -1e30f;
        #pragma unroll
        for (int j = 0; j < NPL; ++j) {
            vals[j] = sh_score[rr][lane + 32 * j];
            m = fmaxf(m, vals[j]);
        }
        #pragma unroll
        for (int off = 16; off > 0; off >>= 1)
            m = fmaxf(m, __shfl_xor_sync(0xFFFFFFFFu, m, off));

        float sum = 0.0f;
        #pragma unroll
        for (int j = 0; j < NPL; ++j) {
            vals[j] = __expf(vals[j] - m);
            sum += vals[j];
        }
        #pragma unroll
        for (int off = 16; off > 0; off >>= 1)
            sum += __shfl_xor_sync(0xFFFFFFFFu, sum, off);

        float inv = __frcp_rn(sum);
        float* arow = attn_out + (size_t)(bh * T + t0 + rr) * S;
        #pragma unroll
        for (int j = 0; j < NPL; ++j) {
            float a = vals[j] * inv;
            sh_score[rr][lane + 32 * j] = a;
            arow[lane + 32 * j] = a;
        }
    }
    __syncthreads();   // scores final; phase-1 union dead -> AV partials

    // ---- AV: out[t][d] = sum_s attn[t][s] * value[s][d] ----
    // 8 s-groups; groups 0-3 store partials, groups 4-7 add in-place, then
    // group 0 folds the 4 slots. Partials reuse sh_u[0..4095].
    {
        const int d  = tid & 63;
        const int sg = tid >> 6;   // 0..7
        float acc[TTB];
        #pragma unroll
        for (int tt = 0; tt < TTB; ++tt) acc[tt] = 0.0f;

        const float* vbase = value + (size_t)bh * S * D + d;
        for (int s4 = sg * 4; s4 < S; s4 += 32) {
            float v0 = __ldg(vbase + (size_t)(s4 + 0) * D);
            float v1 = __ldg(vbase + (size_t)(s4 + 1) * D);
            float v2 = __ldg(vbase + (size_t)(s4 + 2) * D);
            float v3 = __ldg(vbase + (size_t)(s4 + 3) * D);
            #pragma unroll
            for (int tt = 0; tt < TTB; ++tt) {
                float4 a = *(const float4*)&sh_score[tt][s4];
                float t = fmaf(a.x, v0, fmaf(a.y, v1, fmaf(a.z, v2, a.w * v3)));
                acc[tt] += t;
            }
        }

        if (sg < 4) {
            #pragma unroll
            for (int tt = 0; tt < TTB; ++tt)
                sh_u[(sg * TTB + tt) * 64 + d] = acc[tt];
        }
        __syncthreads();
        if (sg >= 4) {
            #pragma unroll
            for (int tt = 0; tt < TTB; ++tt)
                sh_u[((sg - 4) * TTB + tt) * 64 + d] += acc[tt];
        }
        __syncthreads();

        if (sg == 0) {
            #pragma unroll
            for (int tt = 0; tt < TTB; ++tt) {
                float o = sh_u[(0 * TTB + tt) * 64 + d]
                        + sh_u[(1 * TTB + tt) * 64 + d]
                        + sh_u[(2 * TTB + tt) * 64 + d]
                        + sh_u[(3 * TTB + tt) * 64 + d];
                out[(size_t)(bh * T + t0 + tt) * D + d] = o;
            }
        }
    }
}

// ---------------------------------------------------------------------------
extern "C" void kernel_launch(void* const* d_in, const int* in_sizes, int n_in,
                              void* d_out, int out_size) {
    const float* query = (const float*)d_in[0];
    const float* key   = (const float*)d_in[1];
    const float* value = (const float*)d_in[2];
    const float* Wq    = (const float*)d_in[3];
    const float* Wk    = (const float*)d_in[4];
    const float* v_w   = (const float*)d_in[5];

    float* out_ptr  = (float*)d_out;                       // (b,h,t,d)
    float* attn_ptr = (float*)d_out + (size_t)BH * T * D;  // (b,h,t,s)

    proj_kernel<<<256, 256>>>(query, key, Wq, Wk);
    attn_kernel<<<NBLK, 512>>>(value, v_w, out_ptr, attn_ptr);
}